// round 16
// baseline (speedup 1.0000x reference)
#include <cuda_runtime.h>
#include <cstdint>

#define N_NODES 40000
#define N_EDGES 640000
#define D 128
#define N_OPS 5
#define EPS 1e-5f
#define FLT_BIG 3.402823466e38f
#define SCAN_BLOCKS 160
#define SCAN_CHUNK 250           // SCAN_BLOCKS * SCAN_CHUNK == N_NODES
#define STAT_BLOCKS 320
#define STAT_CHUNK (N_NODES / STAT_BLOCKS)   // 125
#define HIST_BLOCKS 2500
#define SQ_SIZE (2 * N_OPS * D)  // 1280

// ---------------- scratch (static device globals; zero-init at load) -------
// Replay invariant: every structure is re-zeroed by the LAST kernel that
// touches it, so each graph replay starts from the same state with no
// dedicated init launch.
__device__ int      g_deg[N_NODES];        // zeroed by k_final after last read
__device__ int      g_offs[N_NODES + 1];   // overwritten每 replay by k_scan
__device__ int      g_cursor[N_NODES];     // overwritten every replay by k_scan
__device__ int      g_csr_src[N_EDGES];
__device__ unsigned g_flag[SCAN_BLOCKS];   // zeroed by k_stats2 elected block
__device__ float    g_sum[(size_t)N_NODES * D];
__device__ float    g_max[(size_t)N_NODES * D];
__device__ float    g_SQ[SQ_SIZE];         // zeroed by k_stats2 elected block
__device__ float    g_A[N_OPS * D];
__device__ float    g_C[N_OPS * D];
__device__ unsigned g_elect;               // reset by k_stats2 elected block

// ---------------- 1. heterogeneous: h/hin stats || degree histogram -------
// Blocks [0, STAT_BLOCKS): BN stats for graph-independent branches 0/1 —
// overlap the histogram's atomic phase (lowest block indices -> wave 1).
// Blocks [STAT_BLOCKS, ...): degree histogram. edge_index is int32 (verified
// by dtype sniff in rounds 7-14; out-of-range guards remain as safety net).
__global__ void k_hist_st(const int* __restrict__ ei,
                          const float* __restrict__ h,
                          const float* __restrict__ hin) {
    if (blockIdx.x < STAT_BLOCKS) {
        int blk  = blockIdx.x;
        int d    = threadIdx.x & 127;        // feature
        int half = threadIdx.x >> 7;         // 0/1: split the node range
        int n0 = blk * STAT_CHUNK;
        float s0 = 0.f, q0 = 0.f, s1 = 0.f, q1 = 0.f;
        for (int n = n0 + half; n < n0 + STAT_CHUNK; n += 2) {
            size_t o = (size_t)n * D + d;
            float x0 = h[o];
            float x1 = hin[o];
            s0 += x0; q0 += x0 * x0;
            s1 += x1; q1 += x1 * x1;
        }
        atomicAdd(&g_SQ[0 * D + d], s0);
        atomicAdd(&g_SQ[(N_OPS + 0) * D + d], q0);
        atomicAdd(&g_SQ[1 * D + d], s1);
        atomicAdd(&g_SQ[(N_OPS + 1) * D + d], q1);
    } else {
        int e = (blockIdx.x - STAT_BLOCKS) * blockDim.x + threadIdx.x;
        if (e < N_EDGES) {
            int dst = ei[N_EDGES + e];
            if ((unsigned)dst < N_NODES) atomicAdd(&g_deg[dst], 1);
        }
    }
}

// ---------------- 2. single-pass exclusive scan (decoupled lookback) ------
__global__ void k_scan() {
    __shared__ int wtot[8], wexc[8], rtot[8];
    __shared__ int s_csum, s_boff;
    int b = blockIdx.x, tid = threadIdx.x;  // 256 threads
    int lane = tid & 31, wid = tid >> 5;
    int base = b * SCAN_CHUNK;

    // in-chunk exclusive scan, 1 element / thread
    int d = (tid < SCAN_CHUNK) ? g_deg[base + tid] : 0;
    int v = d;
    #pragma unroll
    for (int o = 1; o < 32; o <<= 1) {
        int t = __shfl_up_sync(0xffffffffu, v, o);
        if (lane >= o) v += t;
    }
    if (lane == 31) wtot[wid] = v;
    __syncthreads();
    if (tid == 0) {
        int run = 0;
        #pragma unroll
        for (int i = 0; i < 8; i++) { int t = wtot[i]; wexc[i] = run; run += t; }
        s_csum = run;
        atomicExch(&g_flag[b], (unsigned)(run + 1));  // publish (0 = not ready)
    }
    __syncthreads();

    // lookback: thread i polls chunk i's flag (i < b), then block-reduce
    int pv = 0;
    if (tid < b) {
        unsigned f;
        do { f = atomicAdd(&g_flag[tid], 0u); } while (f == 0u);
        pv = (int)f - 1;
    }
    int r = pv;
    #pragma unroll
    for (int o = 16; o; o >>= 1) r += __shfl_down_sync(0xffffffffu, r, o);
    if (lane == 0) rtot[wid] = r;
    __syncthreads();
    if (tid == 0) {
        int s = 0;
        #pragma unroll
        for (int i = 0; i < 8; i++) s += rtot[i];
        s_boff = s;
        if (b == SCAN_BLOCKS - 1) g_offs[N_NODES] = s + s_csum;
    }
    __syncthreads();

    if (tid < SCAN_CHUNK) {
        int off = s_boff + wexc[wid] + (v - d);
        g_offs[base + tid]   = off;
        g_cursor[base + tid] = off;
    }
}

// ---------------- 3. fill CSR source lists --------------------------------
__global__ void k_fill(const int* __restrict__ ei) {
    int e = blockIdx.x * blockDim.x + threadIdx.x;
    if (e < N_EDGES) {
        int src = ei[e];
        int dst = ei[N_EDGES + e];
        if ((unsigned)dst < N_NODES && (unsigned)src < N_NODES) {
            int pos = atomicAdd(&g_cursor[dst], 1);
            g_csr_src[pos] = src;
        }
    }
}

// ---------------- 4. lean per-node warp aggregation (sum + max) -----------
// Warp per node, 4-wide edge unroll (MLP=4), no smem, low regs -> high occ.
#define ACC(S, M, V) \
    S.x += V.x; S.y += V.y; S.z += V.z; S.w += V.w; \
    M.x = fmaxf(M.x, V.x); M.y = fmaxf(M.y, V.y);   \
    M.z = fmaxf(M.z, V.z); M.w = fmaxf(M.w, V.w);

__global__ void k_agg(const float* __restrict__ h) {
    int warp = (blockIdx.x * blockDim.x + threadIdx.x) >> 5;
    int lane = threadIdx.x & 31;
    if (warp >= N_NODES) return;

    int start = g_offs[warp];
    int end   = g_offs[warp + 1];

    float4 s0 = make_float4(0.f, 0.f, 0.f, 0.f), s1 = s0;
    float4 m0 = make_float4(-FLT_BIG, -FLT_BIG, -FLT_BIG, -FLT_BIG), m1 = m0;

    const float* hp = h + lane * 4;

    for (int b = start; b < end; b += 32) {
        int idx = b + lane;
        int sv  = (idx < end) ? g_csr_src[idx] : 0;
        int cnt = min(32, end - b);
        int k = 0;
        for (; k + 4 <= cnt; k += 4) {
            int ia = __shfl_sync(0xffffffffu, sv, k);
            int ib = __shfl_sync(0xffffffffu, sv, k + 1);
            int ic = __shfl_sync(0xffffffffu, sv, k + 2);
            int id = __shfl_sync(0xffffffffu, sv, k + 3);
            const float4 va = *reinterpret_cast<const float4*>(hp + (size_t)ia * D);
            const float4 vb = *reinterpret_cast<const float4*>(hp + (size_t)ib * D);
            const float4 vc = *reinterpret_cast<const float4*>(hp + (size_t)ic * D);
            const float4 vd = *reinterpret_cast<const float4*>(hp + (size_t)id * D);
            ACC(s0, m0, va) ACC(s1, m1, vb) ACC(s0, m0, vc) ACC(s1, m1, vd)
        }
        for (; k < cnt; k++) {
            int ia = __shfl_sync(0xffffffffu, sv, k);
            const float4 va = *reinterpret_cast<const float4*>(hp + (size_t)ia * D);
            ACC(s0, m0, va)
        }
    }

    float4 s = make_float4(s0.x + s1.x, s0.y + s1.y, s0.z + s1.z, s0.w + s1.w);
    float4 m = make_float4(fmaxf(m0.x, m1.x), fmaxf(m0.y, m1.y),
                           fmaxf(m0.z, m1.z), fmaxf(m0.w, m1.w));
    if (end == start) m = make_float4(0.f, 0.f, 0.f, 0.f);  // empty segment -> 0

    size_t o = (size_t)warp * D + lane * 4;
    *reinterpret_cast<float4*>(g_sum + o) = s;
    *reinterpret_cast<float4*>(g_max + o) = m;
}

// ---------------- 5. BN stats 2/3/4 + elected finalize --------------------
// All blocks accumulate into g_SQ; the LAST block to finish (atomicAdd-rank
// election) computes the fused BN coefficients A/C once, then re-zeroes
// g_SQ/g_flag and resets the election counter for the next graph replay.
__global__ void k_stats2(const float* __restrict__ w,
                         const float* __restrict__ gamma,
                         const float* __restrict__ beta) {
    int tid  = threadIdx.x;
    int d    = tid & 127;
    int half = tid >> 7;
    int n0 = blockIdx.x * STAT_CHUNK;

    float s2 = 0.f, q2 = 0.f, s3 = 0.f, q3 = 0.f, s4 = 0.f, q4 = 0.f;
    for (int n = n0 + half; n < n0 + STAT_CHUNK; n += 2) {
        size_t o = (size_t)n * D + d;
        float x2 = g_sum[o];
        float inv = 1.0f / fmaxf((float)g_deg[n], 1.0f);
        float x3 = x2 * inv;
        float x4 = g_max[o];
        s2 += x2; q2 += x2 * x2;
        s3 += x3; q3 += x3 * x3;
        s4 += x4; q4 += x4 * x4;
    }
    atomicAdd(&g_SQ[2 * D + d], s2);
    atomicAdd(&g_SQ[(N_OPS + 2) * D + d], q2);
    atomicAdd(&g_SQ[3 * D + d], s3);
    atomicAdd(&g_SQ[(N_OPS + 3) * D + d], q3);
    atomicAdd(&g_SQ[4 * D + d], s4);
    atomicAdd(&g_SQ[(N_OPS + 4) * D + d], q4);

    // election: last block to arrive finalizes
    __shared__ unsigned rank;
    __syncthreads();
    if (tid == 0) {
        __threadfence();
        rank = atomicAdd(&g_elect, 1u);
    }
    __syncthreads();
    if (rank == STAT_BLOCKS - 1) {
        // all stats blocks (this kernel) have fenced+arrived; st01 stats
        // landed in the previous kernel. g_SQ is complete.
        for (int t = tid; t < N_OPS * D; t += 256) {
            int b = t / D;
            float S = g_SQ[t];
            float Q = g_SQ[N_OPS * D + t];
            float mu   = S * (1.0f / N_NODES);
            float var  = fmaxf(Q * (1.0f / N_NODES) - mu * mu, 0.0f);
            float rstd = rsqrtf(var + EPS);
            float A = w[b] * gamma[t] * rstd;   // weights >= 0, fold inside ReLU
            g_A[t] = A;
            g_C[t] = w[b] * beta[t] - A * mu;
            g_SQ[t] = 0.0f;                     // reset for next replay
            g_SQ[N_OPS * D + t] = 0.0f;
        }
        for (int t = tid; t < SCAN_BLOCKS; t += 256) g_flag[t] = 0u;
        if (tid == 0) g_elect = 0u;
    }
}

// ---------------- 6. normalize + ReLU + weighted sum ----------------------
// Reads precomputed A/C; zeroes g_deg after its last use (node group = one
// warp, so read -> __syncwarp -> lane-0 zero is race-free).
__global__ void k_final(const float* __restrict__ h, const float* __restrict__ hin,
                        float* __restrict__ out) {
    __shared__ float sA[N_OPS * D];
    __shared__ float sC[N_OPS * D];
    for (int t = threadIdx.x; t < N_OPS * D; t += blockDim.x) {
        sA[t] = g_A[t];
        sC[t] = g_C[t];
    }
    __syncthreads();

    int gid = blockIdx.x * blockDim.x + threadIdx.x;  // 5000*256 = exact
    int n  = gid >> 5;
    int f4 = (gid & 31) * 4;
    size_t o = (size_t)n * D + f4;

    float4 x0 = *reinterpret_cast<const float4*>(h + o);
    float4 x1 = *reinterpret_cast<const float4*>(hin + o);
    float4 x2 = *reinterpret_cast<const float4*>(g_sum + o);
    float4 x4 = *reinterpret_cast<const float4*>(g_max + o);
    int   dg  = g_deg[n];
    __syncwarp();
    if (f4 == 0) g_deg[n] = 0;                 // reset for next replay
    float inv = 1.0f / fmaxf((float)dg, 1.0f);
    float4 x3 = make_float4(x2.x * inv, x2.y * inv, x2.z * inv, x2.w * inv);

    float xs[N_OPS][4] = {
        {x0.x, x0.y, x0.z, x0.w},
        {x1.x, x1.y, x1.z, x1.w},
        {x2.x, x2.y, x2.z, x2.w},
        {x3.x, x3.y, x3.z, x3.w},
        {x4.x, x4.y, x4.z, x4.w},
    };
    float acc[4] = {0.f, 0.f, 0.f, 0.f};
    #pragma unroll
    for (int b = 0; b < N_OPS; b++) {
        #pragma unroll
        for (int c = 0; c < 4; c++) {
            float A = sA[b * D + f4 + c];
            float C = sC[b * D + f4 + c];
            acc[c] += fmaxf(fmaf(A, xs[b][c], C), 0.0f);
        }
    }
    *reinterpret_cast<float4*>(out + o) = make_float4(acc[0], acc[1], acc[2], acc[3]);
}

// ---------------- launch ---------------------------------------------------
extern "C" void kernel_launch(void* const* d_in, const int* in_sizes, int n_in,
                              void* d_out, int out_size) {
    const float* weights = (const float*)d_in[0];
    const int*   ei      = (const int*)d_in[1];     // int32 (verified R7-R14)
    const float* h       = (const float*)d_in[2];
    const float* hin     = (const float*)d_in[3];
    const float* gamma   = (const float*)d_in[4];
    const float* beta    = (const float*)d_in[5];
    float*       out     = (float*)d_out;

    k_hist_st<<<STAT_BLOCKS + HIST_BLOCKS, 256>>>(ei, h, hin);
    k_scan<<<SCAN_BLOCKS, 256>>>();
    k_fill<<<(N_EDGES + 255) / 256, 256>>>(ei);
    k_agg<<<(N_NODES * 32 + 255) / 256, 256>>>(h);
    k_stats2<<<STAT_BLOCKS, 256>>>(weights, gamma, beta);
    k_final<<<N_NODES * D / 4 / 256, 256>>>(h, hin, out);
}

// round 17
// speedup vs baseline: 1.1534x; 1.1534x over previous
#include <cuda_runtime.h>
#include <cstdint>

#define N_NODES 40000
#define N_EDGES 640000
#define D 128
#define N_OPS 5
#define EPS 1e-5f
#define FLT_BIG 3.402823466e38f
#define SCAN_BLOCKS 160
#define SCAN_CHUNK 250           // SCAN_BLOCKS * SCAN_CHUNK == N_NODES
#define STAT_BLOCKS 320
#define STAT_CHUNK (N_NODES / STAT_BLOCKS)   // 125
#define HIST_BLOCKS 2500
#define SQ_SIZE (2 * N_OPS * D)  // 1280

// ---------------- scratch (static device globals; no runtime allocation) ---
__device__ int      g_is32;           // 1 if edge_index is int32, 0 if int64
__device__ int      g_deg[N_NODES];
__device__ int      g_offs[N_NODES + 1];
__device__ int      g_cursor[N_NODES];
__device__ int      g_csr_src[N_EDGES];
__device__ unsigned g_flag[SCAN_BLOCKS];   // lookback: chunk_sum+1 (0 = not ready)
__device__ float    g_sum[(size_t)N_NODES * D];
__device__ float    g_max[(size_t)N_NODES * D];
__device__ float    g_SQ[SQ_SIZE];         // [s0..4 | q0..4][d], atomic-accumulated

// ---------------- 1. init: zero scratch + detect dtype --------------------
__global__ void k_init(const long long* __restrict__ ei) {
    int i = blockIdx.x * blockDim.x + threadIdx.x;
    if (i < N_NODES) g_deg[i] = 0;
    if (i < SQ_SIZE) g_SQ[i] = 0.0f;
    if (i < SCAN_BLOCKS) g_flag[i] = 0u;
    if (blockIdx.x == 0 && threadIdx.x < 32) {
        int lane = threadIdx.x;
        int bad = 0;
        #pragma unroll
        for (int j = 0; j < 8; j++) {
            long long v = ei[lane * 8 + j];
            bad |= (v < 0 || v >= N_NODES) ? 1 : 0;
        }
        unsigned m = __ballot_sync(0xffffffffu, bad);
        if (lane == 0) g_is32 = (m != 0u) ? 1 : 0;
    }
}

__device__ __forceinline__ int load_idx(const void* ei, int pos, int is32) {
    if (is32) return ((const int*)ei)[pos];
    return (int)((const long long*)ei)[pos];
}

// ---------------- 2. heterogeneous: h/hin stats || degree histogram -------
// Blocks [0, STAT_BLOCKS): BN stats for graph-independent branches 0/1 —
// overlap the histogram's atomic phase (lowest block indices -> wave 1).
// Blocks [STAT_BLOCKS, ...): degree histogram.
__global__ void k_hist_st(const void* __restrict__ ei,
                          const float* __restrict__ h,
                          const float* __restrict__ hin) {
    if (blockIdx.x < STAT_BLOCKS) {
        int blk  = blockIdx.x;
        int d    = threadIdx.x & 127;        // feature
        int half = threadIdx.x >> 7;         // 0/1: split the node range
        int n0 = blk * STAT_CHUNK;
        float s0 = 0.f, q0 = 0.f, s1 = 0.f, q1 = 0.f;
        for (int n = n0 + half; n < n0 + STAT_CHUNK; n += 2) {
            size_t o = (size_t)n * D + d;
            float x0 = h[o];
            float x1 = hin[o];
            s0 += x0; q0 += x0 * x0;
            s1 += x1; q1 += x1 * x1;
        }
        atomicAdd(&g_SQ[0 * D + d], s0);
        atomicAdd(&g_SQ[(N_OPS + 0) * D + d], q0);
        atomicAdd(&g_SQ[1 * D + d], s1);
        atomicAdd(&g_SQ[(N_OPS + 1) * D + d], q1);
    } else {
        int e = (blockIdx.x - STAT_BLOCKS) * blockDim.x + threadIdx.x;
        if (e < N_EDGES) {
            int dst = load_idx(ei, N_EDGES + e, g_is32);
            if ((unsigned)dst < N_NODES) atomicAdd(&g_deg[dst], 1);
        }
    }
}

// ---------------- 3. single-pass exclusive scan (decoupled lookback) ------
__global__ void k_scan() {
    __shared__ int wtot[8], wexc[8], rtot[8];
    __shared__ int s_csum, s_boff;
    int b = blockIdx.x, tid = threadIdx.x;  // 256 threads
    int lane = tid & 31, wid = tid >> 5;
    int base = b * SCAN_CHUNK;

    // in-chunk exclusive scan, 1 element / thread
    int d = (tid < SCAN_CHUNK) ? g_deg[base + tid] : 0;
    int v = d;
    #pragma unroll
    for (int o = 1; o < 32; o <<= 1) {
        int t = __shfl_up_sync(0xffffffffu, v, o);
        if (lane >= o) v += t;
    }
    if (lane == 31) wtot[wid] = v;
    __syncthreads();
    if (tid == 0) {
        int run = 0;
        #pragma unroll
        for (int i = 0; i < 8; i++) { int t = wtot[i]; wexc[i] = run; run += t; }
        s_csum = run;
        atomicExch(&g_flag[b], (unsigned)(run + 1));  // publish (0 = not ready)
    }
    __syncthreads();

    // lookback: thread i polls chunk i's flag (i < b), then block-reduce
    int pv = 0;
    if (tid < b) {
        unsigned f;
        do { f = atomicAdd(&g_flag[tid], 0u); } while (f == 0u);
        pv = (int)f - 1;
    }
    int r = pv;
    #pragma unroll
    for (int o = 16; o; o >>= 1) r += __shfl_down_sync(0xffffffffu, r, o);
    if (lane == 0) rtot[wid] = r;
    __syncthreads();
    if (tid == 0) {
        int s = 0;
        #pragma unroll
        for (int i = 0; i < 8; i++) s += rtot[i];
        s_boff = s;
        if (b == SCAN_BLOCKS - 1) g_offs[N_NODES] = s + s_csum;
    }
    __syncthreads();

    if (tid < SCAN_CHUNK) {
        int off = s_boff + wexc[wid] + (v - d);
        g_offs[base + tid]   = off;
        g_cursor[base + tid] = off;
    }
}

// ---------------- 4. fill CSR source lists --------------------------------
__global__ void k_fill(const void* __restrict__ ei) {
    int e = blockIdx.x * blockDim.x + threadIdx.x;
    if (e < N_EDGES) {
        int is32 = g_is32;
        int src = load_idx(ei, e, is32);
        int dst = load_idx(ei, N_EDGES + e, is32);
        if ((unsigned)dst < N_NODES && (unsigned)src < N_NODES) {
            int pos = atomicAdd(&g_cursor[dst], 1);
            g_csr_src[pos] = src;
        }
    }
}

// ---------------- 5. lean per-node warp aggregation (sum + max) -----------
// Warp per node, 4-wide edge unroll (MLP=4), no smem, low regs -> high occ.
#define ACC(S, M, V) \
    S.x += V.x; S.y += V.y; S.z += V.z; S.w += V.w; \
    M.x = fmaxf(M.x, V.x); M.y = fmaxf(M.y, V.y);   \
    M.z = fmaxf(M.z, V.z); M.w = fmaxf(M.w, V.w);

__global__ void k_agg(const float* __restrict__ h) {
    int warp = (blockIdx.x * blockDim.x + threadIdx.x) >> 5;
    int lane = threadIdx.x & 31;
    if (warp >= N_NODES) return;

    int start = g_offs[warp];
    int end   = g_offs[warp + 1];

    float4 s0 = make_float4(0.f, 0.f, 0.f, 0.f), s1 = s0;
    float4 m0 = make_float4(-FLT_BIG, -FLT_BIG, -FLT_BIG, -FLT_BIG), m1 = m0;

    const float* hp = h + lane * 4;

    for (int b = start; b < end; b += 32) {
        int idx = b + lane;
        int sv  = (idx < end) ? g_csr_src[idx] : 0;
        int cnt = min(32, end - b);
        int k = 0;
        for (; k + 4 <= cnt; k += 4) {
            int ia = __shfl_sync(0xffffffffu, sv, k);
            int ib = __shfl_sync(0xffffffffu, sv, k + 1);
            int ic = __shfl_sync(0xffffffffu, sv, k + 2);
            int id = __shfl_sync(0xffffffffu, sv, k + 3);
            const float4 va = *reinterpret_cast<const float4*>(hp + (size_t)ia * D);
            const float4 vb = *reinterpret_cast<const float4*>(hp + (size_t)ib * D);
            const float4 vc = *reinterpret_cast<const float4*>(hp + (size_t)ic * D);
            const float4 vd = *reinterpret_cast<const float4*>(hp + (size_t)id * D);
            ACC(s0, m0, va) ACC(s1, m1, vb) ACC(s0, m0, vc) ACC(s1, m1, vd)
        }
        for (; k < cnt; k++) {
            int ia = __shfl_sync(0xffffffffu, sv, k);
            const float4 va = *reinterpret_cast<const float4*>(hp + (size_t)ia * D);
            ACC(s0, m0, va)
        }
    }

    float4 s = make_float4(s0.x + s1.x, s0.y + s1.y, s0.z + s1.z, s0.w + s1.w);
    float4 m = make_float4(fmaxf(m0.x, m1.x), fmaxf(m0.y, m1.y),
                           fmaxf(m0.z, m1.z), fmaxf(m0.w, m1.w));
    if (end == start) m = make_float4(0.f, 0.f, 0.f, 0.f);  // empty segment -> 0

    size_t o = (size_t)warp * D + lane * 4;
    *reinterpret_cast<float4*>(g_sum + o) = s;
    *reinterpret_cast<float4*>(g_max + o) = m;
}

// ---------------- 6. BN stats for graph branches 2/3/4 --------------------
// Reads only g_sum/g_max/deg (41 MB, L2-hot right after k_agg).
__global__ void k_stats2() {
    int blk  = blockIdx.x;
    int d    = threadIdx.x & 127;
    int half = threadIdx.x >> 7;
    int n0 = blk * STAT_CHUNK;

    float s2 = 0.f, q2 = 0.f, s3 = 0.f, q3 = 0.f, s4 = 0.f, q4 = 0.f;
    for (int n = n0 + half; n < n0 + STAT_CHUNK; n += 2) {
        size_t o = (size_t)n * D + d;
        float x2 = g_sum[o];
        float inv = 1.0f / fmaxf((float)g_deg[n], 1.0f);
        float x3 = x2 * inv;
        float x4 = g_max[o];
        s2 += x2; q2 += x2 * x2;
        s3 += x3; q3 += x3 * x3;
        s4 += x4; q4 += x4 * x4;
    }
    atomicAdd(&g_SQ[2 * D + d], s2);
    atomicAdd(&g_SQ[(N_OPS + 2) * D + d], q2);
    atomicAdd(&g_SQ[3 * D + d], s3);
    atomicAdd(&g_SQ[(N_OPS + 3) * D + d], q3);
    atomicAdd(&g_SQ[4 * D + d], s4);
    atomicAdd(&g_SQ[(N_OPS + 4) * D + d], q4);
}

// ---------------- 7. fused coef + normalize + ReLU + weighted sum ---------
__global__ void k_final(const float* __restrict__ h, const float* __restrict__ hin,
                        const float* __restrict__ w,
                        const float* __restrict__ gamma,
                        const float* __restrict__ beta,
                        float* __restrict__ out) {
    __shared__ float sA[N_OPS * D];
    __shared__ float sC[N_OPS * D];
    for (int t = threadIdx.x; t < N_OPS * D; t += blockDim.x) {
        int b = t / D;
        float S = g_SQ[t];
        float Q = g_SQ[N_OPS * D + t];
        float mu   = S * (1.0f / N_NODES);
        float var  = fmaxf(Q * (1.0f / N_NODES) - mu * mu, 0.0f);
        float rstd = rsqrtf(var + EPS);
        float A = w[b] * gamma[t] * rstd;   // weights >= 0, fold inside ReLU
        sA[t] = A;
        sC[t] = w[b] * beta[t] - A * mu;
    }
    __syncthreads();

    int gid = blockIdx.x * blockDim.x + threadIdx.x;  // one float4 per thread
    if (gid >= N_NODES * (D / 4)) return;
    int n  = gid >> 5;
    int f4 = (gid & 31) * 4;
    size_t o = (size_t)n * D + f4;

    float4 x0 = *reinterpret_cast<const float4*>(h + o);
    float4 x1 = *reinterpret_cast<const float4*>(hin + o);
    float4 x2 = *reinterpret_cast<const float4*>(g_sum + o);
    float4 x4 = *reinterpret_cast<const float4*>(g_max + o);
    float inv = 1.0f / fmaxf((float)g_deg[n], 1.0f);
    float4 x3 = make_float4(x2.x * inv, x2.y * inv, x2.z * inv, x2.w * inv);

    float xs[N_OPS][4] = {
        {x0.x, x0.y, x0.z, x0.w},
        {x1.x, x1.y, x1.z, x1.w},
        {x2.x, x2.y, x2.z, x2.w},
        {x3.x, x3.y, x3.z, x3.w},
        {x4.x, x4.y, x4.z, x4.w},
    };
    float acc[4] = {0.f, 0.f, 0.f, 0.f};
    #pragma unroll
    for (int b = 0; b < N_OPS; b++) {
        #pragma unroll
        for (int c = 0; c < 4; c++) {
            float A = sA[b * D + f4 + c];
            float C = sC[b * D + f4 + c];
            acc[c] += fmaxf(fmaf(A, xs[b][c], C), 0.0f);
        }
    }
    *reinterpret_cast<float4*>(out + o) = make_float4(acc[0], acc[1], acc[2], acc[3]);
}

// ---------------- launch ---------------------------------------------------
extern "C" void kernel_launch(void* const* d_in, const int* in_sizes, int n_in,
                              void* d_out, int out_size) {
    const float* weights = (const float*)d_in[0];
    const void*  ei      = d_in[1];                 // int32 or int64, detected on-device
    const float* h       = (const float*)d_in[2];
    const float* hin     = (const float*)d_in[3];
    const float* gamma   = (const float*)d_in[4];
    const float* beta    = (const float*)d_in[5];
    float*       out     = (float*)d_out;

    k_init<<<(N_NODES + 255) / 256, 256>>>((const long long*)ei);
    k_hist_st<<<STAT_BLOCKS + HIST_BLOCKS, 256>>>(ei, h, hin);
    k_scan<<<SCAN_BLOCKS, 256>>>();
    k_fill<<<(N_EDGES + 255) / 256, 256>>>(ei);
    k_agg<<<(N_NODES * 32 + 255) / 256, 256>>>(h);
    k_stats2<<<STAT_BLOCKS, 256>>>();
    k_final<<<(N_NODES * (D / 4) + 255) / 256, 256>>>(h, hin, weights, gamma, beta, out);
}